// round 10
// baseline (speedup 1.0000x reference)
#include <cuda_runtime.h>
#include <cuda_fp16.h>
#include <cuda_bf16.h>
#include <cstdint>
#include <cstddef>

#define NB    32
#define CIN   13
#define LIN   4096
#define C1    128
#define L1OUT 4094
#define HDIM  256
#define LSEQ  2046
#define G3    768
#define M_GI  (LSEQ*NB)      /* 65472 */
#define M_PAD 65536
#define NCOL  1536
#define K2    384

// ---------------- static device scratch ----------------
__device__ float  g_conv1[(size_t)NB*C1*L1OUT];
__device__ float  g_gi[(size_t)M_GI*NCOL];
__device__ float  g_outf[(size_t)M_GI*HDIM];
__device__ float  g_outb[(size_t)M_GI*HDIM];
__device__ __align__(16) __half2 g_whh16[4*64*G3];           // [dr][kk][row]
__device__ float  g_Bmat[HDIM*NCOL];
__device__ float  g_W2T[K2*HDIM];
__device__ float  g_Cmat[(size_t)K2*NCOL];                   // [k][col]
__device__ __align__(16) __nv_bfloat16 g_Ah[(size_t)M_PAD*K2];
__device__ __align__(16) __nv_bfloat16 g_Al[(size_t)M_PAD*K2];
__device__ __align__(16) __nv_bfloat16 g_Ch[(size_t)NCOL*K2];    // [col][k]
__device__ __align__(16) __nv_bfloat16 g_Cl[(size_t)NCOL*K2];
__device__ float  g_beta[NCOL];
__device__ float  g_beta2[NCOL];
__device__ float  g_bhhn[2*HDIM];

// ---------------- ptx helpers ----------------
__device__ __forceinline__ uint32_t smem_u32(const void* p) {
    uint32_t a;
    asm("{ .reg .u64 t; cvta.to.shared.u64 t, %1; cvt.u32.u64 %0, t; }" : "=r"(a) : "l"(p));
    return a;
}
#define CP_ASYNC16(dst, src) \
    asm volatile("cp.async.cg.shared.global [%0], [%1], 16;" :: "r"(dst), "l"(src) : "memory")
#define CP_ASYNC_COMMIT() asm volatile("cp.async.commit_group;" ::: "memory")
#define CP_ASYNC_WAIT0()  asm volatile("cp.async.wait_group 0;" ::: "memory")

__device__ __forceinline__ void mma16816(float* c, uint32_t a0, uint32_t a1, uint32_t a2, uint32_t a3,
                                         uint32_t b0, uint32_t b1) {
    asm volatile("mma.sync.aligned.m16n8k16.row.col.f32.bf16.bf16.f32 "
        "{%0,%1,%2,%3}, {%4,%5,%6,%7}, {%8,%9}, {%0,%1,%2,%3};"
        : "+f"(c[0]), "+f"(c[1]), "+f"(c[2]), "+f"(c[3])
        : "r"(a0), "r"(a1), "r"(a2), "r"(a3), "r"(b0), "r"(b1));
}

// ---------------- prep ----------------
__global__ void prep_kernel(const float* __restrict__ Whh_f, const float* __restrict__ Whh_b,
                            const float* __restrict__ Wih_f, const float* __restrict__ Wih_b,
                            const float* __restrict__ bih_f, const float* __restrict__ bih_b,
                            const float* __restrict__ bhh_f, const float* __restrict__ bhh_b,
                            const float* __restrict__ W2) {
    int i = blockIdx.x*256 + threadIdx.x;
    if (i < 4*64*G3) {
        int dr  = i / (64*G3);
        int rem = i - dr*(64*G3);
        int kk  = rem / G3;
        int row = rem - kk*G3;
        int d = dr >> 1, r = dr & 1;
        const float* W = d ? Whh_b : Whh_f;
        int c = r*128 + 2*kk;
        g_whh16[i] = __floats2half2_rn(W[row*HDIM + c], W[row*HDIM + c + 1]);
    }
    if (i < HDIM*NCOL) {
        int k = i / NCOL; int col = i - k*NCOL;
        int d = col / G3; int rc = col - d*G3;
        const float* W = d ? Wih_b : Wih_f;
        g_Bmat[i] = W[rc*HDIM + k];
    }
    if (i < K2*HDIM) {
        int kk = i >> 8; int c2 = i & 255;
        g_W2T[i] = W2[c2*K2 + kk];
    }
    if (i < NCOL) {
        int d = i / G3; int rc = i - d*G3;
        const float* bi = d ? bih_b : bih_f;
        const float* bh = d ? bhh_b : bhh_f;
        float v = bi[rc];
        if (rc < 512) v += bh[rc];
        g_beta[i] = v;
    }
    if (i < 2*HDIM) {
        int d = i >> 8; int j = i & 255;
        const float* bh = d ? bhh_b : bhh_f;
        g_bhhn[i] = bh[512 + j];
    }
}

// ---------------- conv1 ----------------
__global__ void __launch_bounds__(256) conv1_kernel(const float* __restrict__ X,
                                                    const float* __restrict__ W1,
                                                    const float* __restrict__ b1) {
    __shared__ float Ws[C1*39];
    __shared__ float Xs[CIN*516];
    int n = blockIdx.x, lt = blockIdx.y, tid = threadIdx.x;
    int l0 = lt*512;
    for (int i = tid; i < C1*39; i += 256) Ws[i] = W1[i];
    for (int i = tid; i < CIN*514; i += 256) {
        int ci = i / 514, off = i - ci*514;
        int g = l0 + off;
        Xs[ci*516 + off] = (g < LIN) ? X[(size_t)(n*CIN + ci)*LIN + g] : 0.f;
    }
    __syncthreads();
    float xa[CIN][3], xb[CIN][3];
    #pragma unroll
    for (int ci = 0; ci < CIN; ci++)
        #pragma unroll
        for (int k = 0; k < 3; k++) {
            xa[ci][k] = Xs[ci*516 + tid + k];
            xb[ci][k] = Xs[ci*516 + tid + 256 + k];
        }
    int l = l0 + tid;
    for (int co = 0; co < C1; co++) {
        float b = __ldg(b1 + co);
        float s0 = b, s1 = b;
        #pragma unroll
        for (int ci = 0; ci < CIN; ci++)
            #pragma unroll
            for (int k = 0; k < 3; k++) {
                float w = Ws[co*39 + ci*3 + k];
                s0 += xa[ci][k]*w;
                s1 += xb[ci][k]*w;
            }
        float* dst = g_conv1 + (size_t)(n*C1 + co)*L1OUT;
        if (l < L1OUT)       dst[l]       = s0;
        if (l + 256 < L1OUT) dst[l + 256] = s1;
    }
}

// ---------------- Cmat = W2T(384x256) . Bmat(256x1536) ----------------
__global__ void __launch_bounds__(256) cmat_kernel(void) {
    __shared__ float As[8][128];
    __shared__ float Bs[8][128];
    int tid = threadIdx.x;
    int tx = tid & 15, ty = tid >> 4;
    int n0 = blockIdx.x * 128, m0 = blockIdx.y * 128;
    float acc[8][8];
    #pragma unroll
    for (int i = 0; i < 8; i++)
        #pragma unroll
        for (int j = 0; j < 8; j++) acc[i][j] = 0.f;
    int arow = tid >> 1, acol = (tid & 1)*4;
    int brow = tid >> 5, bcol = (tid & 31)*4;
    for (int k0 = 0; k0 < HDIM; k0 += 8) {
        float4 av = *(const float4*)&g_W2T[(size_t)(m0 + arow)*HDIM + k0 + acol];
        As[acol+0][arow] = av.x; As[acol+1][arow] = av.y;
        As[acol+2][arow] = av.z; As[acol+3][arow] = av.w;
        *(float4*)&Bs[brow][bcol] = *(const float4*)&g_Bmat[(size_t)(k0 + brow)*NCOL + n0 + bcol];
        __syncthreads();
        #pragma unroll
        for (int k = 0; k < 8; k++) {
            float a[8], b[8];
            *(float4*)&a[0] = *(const float4*)&As[k][ty*4];
            *(float4*)&a[4] = *(const float4*)&As[k][64 + ty*4];
            *(float4*)&b[0] = *(const float4*)&Bs[k][tx*4];
            *(float4*)&b[4] = *(const float4*)&Bs[k][64 + tx*4];
            #pragma unroll
            for (int i = 0; i < 8; i++)
                #pragma unroll
                for (int j = 0; j < 8; j++) acc[i][j] += a[i]*b[j];
        }
        __syncthreads();
    }
    #pragma unroll
    for (int i = 0; i < 8; i++) {
        int mr = m0 + ((i < 4) ? ty*4 + i : 64 + ty*4 + i - 4);
        float* crow = g_Cmat + (size_t)mr*NCOL + n0;
        float4 v0, v1;
        v0.x=acc[i][0]; v0.y=acc[i][1]; v0.z=acc[i][2]; v0.w=acc[i][3];
        v1.x=acc[i][4]; v1.y=acc[i][5]; v1.z=acc[i][6]; v1.w=acc[i][7];
        *(float4*)&crow[tx*4]      = v0;
        *(float4*)&crow[64 + tx*4] = v1;
    }
}

// ---------------- Cmat -> bf16 hi/lo, transposed to [col][k] ----------------
__global__ void cconv_kernel(void) {
    int idx = blockIdx.x*256 + threadIdx.x;
    if (idx < NCOL*K2) {
        int col = idx / K2, k = idx - col*K2;
        float v = g_Cmat[(size_t)k*NCOL + col];
        __nv_bfloat16 hi = __float2bfloat16(v);
        float lo = v - __bfloat162float(hi);
        g_Ch[idx] = hi;
        g_Cl[idx] = __float2bfloat16(lo);
    }
}

// ---------------- beta2 ----------------
__global__ void beta2_kernel(const float* __restrict__ b2) {
    int col = blockIdx.x*256 + threadIdx.x;
    if (col >= NCOL) return;
    float s = g_beta[col];
    for (int k = 0; k < HDIM; k++)
        s += __ldg(b2 + k) * g_Bmat[(size_t)k*NCOL + col];
    g_beta2[col] = s;
}

// ---------------- materialize A (im2col) as bf16 hi/lo --------------------
__global__ void __launch_bounds__(256) amat_kernel(void) {
    int group = blockIdx.x;                 // 12288 blocks
    int c16 = group % 48;
    int m = (group / 48) * 256 + threadIdx.x;
    __nv_bfloat16 hi[8], lo[8];
    if (m < M_GI) {
        int nn = m / LSEQ;
        int l2 = m - nn*LSEQ;
        const float* base = g_conv1 + (size_t)nn*C1*L1OUT + 2*l2;
        #pragma unroll
        for (int j = 0; j < 8; j++) {
            int kk = c16*8 + j;
            int ci = kk / 3, kw = kk - ci*3;
            float v = base[(size_t)ci*L1OUT + kw];
            hi[j] = __float2bfloat16(v);
            lo[j] = __float2bfloat16(v - __bfloat162float(hi[j]));
        }
    } else {
        #pragma unroll
        for (int j = 0; j < 8; j++) { hi[j] = __float2bfloat16(0.f); lo[j] = hi[j]; }
    }
    size_t off = (size_t)m*K2 + c16*8;
    *(uint4*)&g_Ah[off] = *(uint4*)hi;
    *(uint4*)&g_Al[off] = *(uint4*)lo;
}

// ---------------- mma.sync GEMM: gi = A(bf16 hi/lo) . C^T(bf16 hi/lo) + beta2 -------
#define GEMM_SMEM (2*4*16384)

__device__ __forceinline__ void fill_tiles(uint32_t dst_base, int m0, int n0, int k0, int tid) {
    const __nv_bfloat16* srcs[4];
    srcs[0] = g_Ah + (size_t)m0*K2 + k0;
    srcs[1] = g_Al + (size_t)m0*K2 + k0;
    srcs[2] = g_Ch + (size_t)n0*K2 + k0;
    srcs[3] = g_Cl + (size_t)n0*K2 + k0;
    #pragma unroll
    for (int mat = 0; mat < 4; mat++) {
        const char* s = (const char*)srcs[mat];
        uint32_t d = dst_base + mat*16384;
        #pragma unroll
        for (int i = 0; i < 4; i++) {
            int idx = tid + i*256;
            int row = idx >> 3, ch = idx & 7;
            uint32_t so = (uint32_t)row*128 + (uint32_t)((ch*16) ^ ((row & 7) << 4));
            CP_ASYNC16(d + so, s + (size_t)row*(K2*2) + ch*16);
        }
    }
}

__global__ void __launch_bounds__(256, 1) tc_gemm_kernel(void) {
    extern __shared__ __align__(16) char sm[];
    uint32_t sb = smem_u32(sm);
    int tid = threadIdx.x;
    int lane = tid & 31, wid = tid >> 5;
    int wm = wid & 1, wn = wid >> 1;          // warp tile 64(m) x 32(n)
    int n0 = blockIdx.x * 128, m0 = blockIdx.y * 128;

    float acc[4][4][4];
    #pragma unroll
    for (int i = 0; i < 4; i++)
        #pragma unroll
        for (int j = 0; j < 4; j++)
            #pragma unroll
            for (int q = 0; q < 4; q++) acc[i][j][q] = 0.f;

    int q = lane >> 3, rr = lane & 7;
    int a_row = wm*64 + (q & 1)*8 + rr;
    int a_cq  = (q >> 1)*16;
    int b_row = wn*32 + (q >> 1)*8 + rr;
    int b_cq  = (q & 1)*16;
    uint32_t a_xor = (uint32_t)(rr << 4);
    uint32_t b_xor = (uint32_t)(rr << 4);

    fill_tiles(sb, m0, n0, 0, tid);
    CP_ASYNC_COMMIT();

    #pragma unroll 1
    for (int c = 0; c < 6; c++) {
        CP_ASYNC_WAIT0();
        __syncthreads();
        if (c < 5) {
            fill_tiles(sb + ((c + 1) & 1)*65536, m0, n0, (c + 1)*64, tid);
            CP_ASYNC_COMMIT();
        }
        uint32_t tb = sb + (c & 1)*65536;
        #pragma unroll
        for (int kf = 0; kf < 4; kf++) {
            uint32_t Ah_f[4][4], Al_f[4][4], Bh_f[2][4], Bl_f[2][4];
            uint32_t acol = (uint32_t)((a_cq + kf*32) ^ a_xor);
            uint32_t bcol = (uint32_t)((b_cq + kf*32) ^ b_xor);
            #pragma unroll
            for (int mf = 0; mf < 4; mf++) {
                uint32_t off = (uint32_t)(a_row + mf*16)*128 + acol;
                asm volatile("ldmatrix.sync.aligned.m8n8.x4.shared.b16 {%0,%1,%2,%3}, [%4];"
                    : "=r"(Ah_f[mf][0]), "=r"(Ah_f[mf][1]), "=r"(Ah_f[mf][2]), "=r"(Ah_f[mf][3])
                    : "r"(tb + off));
                asm volatile("ldmatrix.sync.aligned.m8n8.x4.shared.b16 {%0,%1,%2,%3}, [%4];"
                    : "=r"(Al_f[mf][0]), "=r"(Al_f[mf][1]), "=r"(Al_f[mf][2]), "=r"(Al_f[mf][3])
                    : "r"(tb + 16384 + off));
            }
            #pragma unroll
            for (int nfp = 0; nfp < 2; nfp++) {
                uint32_t off = (uint32_t)(b_row + nfp*16)*128 + bcol;
                asm volatile("ldmatrix.sync.aligned.m8n8.x4.shared.b16 {%0,%1,%2,%3}, [%4];"
                    : "=r"(Bh_f[nfp][0]), "=r"(Bh_f[nfp][1]), "=r"(Bh_f[nfp][2]), "=r"(Bh_f[nfp][3])
                    : "r"(tb + 32768 + off));
                asm volatile("ldmatrix.sync.aligned.m8n8.x4.shared.b16 {%0,%1,%2,%3}, [%4];"
                    : "=r"(Bl_f[nfp][0]), "=r"(Bl_f[nfp][1]), "=r"(Bl_f[nfp][2]), "=r"(Bl_f[nfp][3])
                    : "r"(tb + 49152 + off));
            }
            #pragma unroll
            for (int mf = 0; mf < 4; mf++)
                #pragma unroll
                for (int nf = 0; nf < 4; nf++) {
                    int nfp = nf >> 1, sel = (nf & 1)*2;
                    mma16816(acc[mf][nf], Ah_f[mf][0], Ah_f[mf][1], Ah_f[mf][2], Ah_f[mf][3],
                             Bh_f[nfp][sel], Bh_f[nfp][sel+1]);
                    mma16816(acc[mf][nf], Ah_f[mf][0], Ah_f[mf][1], Ah_f[mf][2], Ah_f[mf][3],
                             Bl_f[nfp][sel], Bl_f[nfp][sel+1]);
                    mma16816(acc[mf][nf], Al_f[mf][0], Al_f[mf][1], Al_f[mf][2], Al_f[mf][3],
                             Bh_f[nfp][sel], Bh_f[nfp][sel+1]);
                }
        }
    }

    int col0 = n0 + wn*32 + (lane & 3)*2;
    int row0 = m0 + wm*64 + (lane >> 2);
    float2 bb[4];
    #pragma unroll
    for (int nf = 0; nf < 4; nf++)
        bb[nf] = *(const float2*)&g_beta2[col0 + nf*8];
    #pragma unroll
    for (int mf = 0; mf < 4; mf++) {
        int mr0 = row0 + mf*16;
        int mr1 = mr0 + 8;
        #pragma unroll
        for (int nf = 0; nf < 4; nf++) {
            int cc = col0 + nf*8;
            if (mr0 < M_GI) {
                float2 v; v.x = acc[mf][nf][0] + bb[nf].x; v.y = acc[mf][nf][1] + bb[nf].y;
                *(float2*)&g_gi[(size_t)mr0*NCOL + cc] = v;
            }
            if (mr1 < M_GI) {
                float2 v; v.x = acc[mf][nf][2] + bb[nf].x; v.y = acc[mf][nf][3] + bb[nf].y;
                *(float2*)&g_gi[(size_t)mr1*NCOL + cc] = v;
            }
        }
    }
}

// ---------------- GRU (R6 proven version: register weights + cluster.sync) ---------
__global__ void __cluster_dims__(2,1,1) __launch_bounds__(256,1)
gru_kernel(void) {
    __shared__ __align__(16) __half2 h2_s[64];
    __shared__ __align__(16) float recv[2*384];

    int tid = threadIdx.x;
    uint32_t rank;
    asm("mov.u32 %0, %%cluster_ctarank;" : "=r"(rank));
    int chain = blockIdx.x >> 1;
    int d = chain >> 5;
    int n = chain & 31;
    int dr = d*2 + (int)rank;

    __half2 w0[64], w1[64], w2[64];
    {
        const __half2* base = g_whh16 + (size_t)dr*64*G3;
        #pragma unroll
        for (int kk = 0; kk < 64; kk++) {
            w0[kk] = base[kk*G3 + tid];
            w1[kk] = base[kk*G3 + tid + 256];
            w2[kk] = base[kk*G3 + tid + 512];
        }
    }
    if (tid < 64) h2_s[tid] = __float2half2_rn(0.f);

    int jj = tid;
    bool own = ((jj >> 7) == (int)rank);
    int jloc = jj & 127;
    float bn = own ? g_bhhn[d*HDIM + jj] : 0.f;
    float* gout = d ? g_outb : g_outf;
    float h_reg = 0.f;
    __half* hh_s = (__half*)h2_s;

    uint32_t recv_u = smem_u32(recv);
    uint32_t pa0 = 0, pa1 = 0;
    {
        uint32_t a0 = recv_u + (uint32_t)jloc*4u;
        uint32_t a1 = recv_u + (384u + (uint32_t)jloc)*4u;
        asm("mapa.shared::cluster.u32 %0, %1, %2;" : "=r"(pa0) : "r"(a0), "r"(rank ^ 1u));
        asm("mapa.shared::cluster.u32 %0, %1, %2;" : "=r"(pa1) : "r"(a1), "r"(rank ^ 1u));
    }
    __syncthreads();

    const uint4* hv4 = (const uint4*)h2_s;

    for (int s = 0; s < LSEQ; s++) {
        int tpos = d ? (LSEQ - 1 - s) : s;
        size_t gbase = ((size_t)(n*LSEQ + tpos))*NCOL + (size_t)d*G3 + jj;
        float gir = 0.f, giz = 0.f, gin = 0.f;
        if (own) {
            gir = __ldg(&g_gi[gbase]);
            giz = __ldg(&g_gi[gbase + 256]);
            gin = __ldg(&g_gi[gbase + 512]);
        }

        float a0 = 0.f, a1 = 0.f, a2 = 0.f;
        #pragma unroll
        for (int g2 = 0; g2 < 2; g2++) {
            __half2 zz = __float2half2_rn(0.f);
            __half2 p00=zz,p01=zz,p10=zz,p11=zz,p20=zz,p21=zz;
            #pragma unroll
            for (int u = 0; u < 8; u++) {
                uint4 hv = hv4[g2*8 + u];
                __half2 ha = *(__half2*)&hv.x;
                __half2 hb = *(__half2*)&hv.y;
                __half2 hc = *(__half2*)&hv.z;
                __half2 hd = *(__half2*)&hv.w;
                int kb = g2*32 + u*4;
                p00 = __hfma2(w0[kb+0], ha, p00);
                p01 = __hfma2(w0[kb+1], hb, p01);
                p00 = __hfma2(w0[kb+2], hc, p00);
                p01 = __hfma2(w0[kb+3], hd, p01);
                p10 = __hfma2(w1[kb+0], ha, p10);
                p11 = __hfma2(w1[kb+1], hb, p11);
                p10 = __hfma2(w1[kb+2], hc, p10);
                p11 = __hfma2(w1[kb+3], hd, p11);
                p20 = __hfma2(w2[kb+0], ha, p20);
                p21 = __hfma2(w2[kb+1], hb, p21);
                p20 = __hfma2(w2[kb+2], hc, p20);
                p21 = __hfma2(w2[kb+3], hd, p21);
            }
            float2 f;
            f = __half22float2(__hadd2(p00, p01)); a0 += f.x + f.y;
            f = __half22float2(__hadd2(p10, p11)); a1 += f.x + f.y;
            f = __half22float2(__hadd2(p20, p21)); a2 += f.x + f.y;
        }

        int buf = (s & 1) * 384;
        if (!own) {
            uint32_t pa = (s & 1) ? pa1 : pa0;
            asm volatile("st.shared::cluster.f32 [%0], %1;" :: "r"(pa),         "f"(a0) : "memory");
            asm volatile("st.shared::cluster.f32 [%0], %1;" :: "r"(pa + 512u),  "f"(a1) : "memory");
            asm volatile("st.shared::cluster.f32 [%0], %1;" :: "r"(pa + 1024u), "f"(a2) : "memory");
        }
        asm volatile("barrier.cluster.arrive.aligned;" ::: "memory");
        asm volatile("barrier.cluster.wait.aligned;"   ::: "memory");
        if (own) {
            float ghr = a0 + recv[buf + jloc];
            float ghz = a1 + recv[buf + 128 + jloc];
            float ghn = a2 + recv[buf + 256 + jloc];
            float r = 1.f/(1.f + __expf(-(gir + ghr)));
            float z = 1.f/(1.f + __expf(-(giz + ghz)));
            float nn2 = tanhf(gin + r*(ghn + bn));
            h_reg = (1.f - z)*nn2 + z*h_reg;
            gout[((size_t)(n*LSEQ + tpos))*HDIM + jj] = h_reg;
            hh_s[jloc] = __float2half_rn(h_reg);
        }
        __syncthreads();
    }
}

// ---------------- combine + hidden_last ----------------
__global__ void __launch_bounds__(256) combine_kernel(float* __restrict__ out) {
    int idx = blockIdx.x*256 + threadIdx.x;
    const int comb = LSEQ*NB*HDIM;
    if (idx < comb) {
        int c = idx & 255;
        int rem = idx >> 8;
        int nn = rem & 31;
        int l = rem >> 5;
        size_t base = ((size_t)(nn*LSEQ + l)) << 8;
        float f = g_outf[base + c];
        float b = g_outb[base + (255 - c)];
        float v = 0.5f*(f + b);
        out[idx] = v > 0.f ? v : 0.f;
    } else if (idx < comb + NB*HDIM) {
        int i2 = idx - comb;
        int nn = i2 >> 8, c = i2 & 255;
        out[idx] = g_outb[((size_t)(nn*LSEQ)) * HDIM + c];
    }
}

// ---------------- launch ----------------
extern "C" void kernel_launch(void* const* d_in, const int* in_sizes, int n_in,
                              void* d_out, int out_size) {
    const float* X     = (const float*)d_in[0];
    const float* W1    = (const float*)d_in[1];
    const float* b1    = (const float*)d_in[2];
    const float* W2    = (const float*)d_in[3];
    const float* b2    = (const float*)d_in[4];
    const float* Wih_f = (const float*)d_in[5];
    const float* Whh_f = (const float*)d_in[6];
    const float* bih_f = (const float*)d_in[7];
    const float* bhh_f = (const float*)d_in[8];
    const float* Wih_b = (const float*)d_in[9];
    const float* Whh_b = (const float*)d_in[10];
    const float* bih_b = (const float*)d_in[11];
    const float* bhh_b = (const float*)d_in[12];
    float* out = (float*)d_out;

    cudaFuncSetAttribute(tc_gemm_kernel, cudaFuncAttributeMaxDynamicSharedMemorySize, GEMM_SMEM);

    prep_kernel<<<1536, 256>>>(Whh_f, Whh_b, Wih_f, Wih_b, bih_f, bih_b, bhh_f, bhh_b, W2);
    conv1_kernel<<<dim3(NB, 8), 256>>>(X, W1, b1);
    cmat_kernel<<<dim3(12, 3), 256>>>();
    cconv_kernel<<<(NCOL*K2 + 255)/256, 256>>>();
    beta2_kernel<<<6, 256>>>(b2);
    amat_kernel<<<12288, 256>>>();
    tc_gemm_kernel<<<dim3(12, 512), 256, GEMM_SMEM>>>();
    gru_kernel<<<128, 256>>>();
    int total = LSEQ*NB*HDIM + NB*HDIM;
    combine_kernel<<<(total + 255)/256, 256>>>(out);
}

// round 11
// speedup vs baseline: 1.3441x; 1.3441x over previous
#include <cuda_runtime.h>
#include <cuda_fp16.h>
#include <cuda_bf16.h>
#include <cstdint>
#include <cstddef>

#define NB    32
#define CIN   13
#define LIN   4096
#define C1    128
#define L1OUT 4094
#define HDIM  256
#define LSEQ  2046
#define G3    768
#define M_GI  (LSEQ*NB)      /* 65472 */
#define M_PAD 65536
#define NCOL  1536
#define K2    384

// ---------------- static device scratch ----------------
__device__ float  g_conv1[(size_t)NB*C1*L1OUT];
__device__ float  g_gi[(size_t)M_GI*NCOL];
__device__ float  g_outf[(size_t)M_GI*HDIM];
__device__ float  g_outb[(size_t)M_GI*HDIM];
__device__ __align__(16) __half2 g_whh16[4*3*64*256];        // [dc][g][kk][t]
__device__ float  g_Bmat[HDIM*NCOL];
__device__ float  g_W2T[K2*HDIM];
__device__ float  g_Cmat[(size_t)K2*NCOL];                   // [k][col]
__device__ __align__(16) __nv_bfloat16 g_Ah[(size_t)M_PAD*K2];
__device__ __align__(16) __nv_bfloat16 g_Al[(size_t)M_PAD*K2];
__device__ __align__(16) __nv_bfloat16 g_Ch[(size_t)NCOL*K2];    // [col][k]
__device__ __align__(16) __nv_bfloat16 g_Cl[(size_t)NCOL*K2];
__device__ float  g_beta[NCOL];
__device__ float  g_beta2[NCOL];
__device__ float  g_bhhn[2*HDIM];

// ---------------- ptx helpers ----------------
__device__ __forceinline__ uint32_t smem_u32(const void* p) {
    uint32_t a;
    asm("{ .reg .u64 t; cvta.to.shared.u64 t, %1; cvt.u32.u64 %0, t; }" : "=r"(a) : "l"(p));
    return a;
}
#define MBARRIER_INIT(mbar_smem_addr, count) \
    asm volatile("mbarrier.init.shared.b64 [%0], %1;" \
        :: "r"((uint32_t)(mbar_smem_addr)), "r"((uint32_t)(count)) : "memory")
#define MBARRIER_WAIT_PARITY_CL(mbar_smem_addr, phase_parity) do { \
    uint32_t _mbar = (uint32_t)(mbar_smem_addr); \
    uint32_t _parity = (uint32_t)(phase_parity); \
    uint32_t _done; \
    asm volatile("{\n\t.reg .pred p;\n\t" \
        "mbarrier.try_wait.parity.acquire.cluster.shared::cta.b64 p, [%1], %2;\n\t" \
        "selp.b32 %0, 1, 0, p;\n\t}" : "=r"(_done) : "r"(_mbar), "r"(_parity) : "memory"); \
    if (!_done) { \
        asm volatile("{\n\t.reg .pred P1;\n\t" \
            "WAIT_LOOP_%=:\n\t" \
            "mbarrier.try_wait.parity.acquire.cluster.shared::cta.b64 P1, [%0], %1, 0x989680;\n\t" \
            "@P1 bra.uni WAIT_DONE_%=;\n\t" \
            "bra.uni WAIT_LOOP_%=;\n\t" \
            "WAIT_DONE_%=:\n\t}" :: "r"(_mbar), "r"(_parity) : "memory"); \
    } \
} while(0)
#define CP_ASYNC16(dst, src) \
    asm volatile("cp.async.cg.shared.global [%0], [%1], 16;" :: "r"(dst), "l"(src) : "memory")
#define CP_ASYNC_COMMIT() asm volatile("cp.async.commit_group;" ::: "memory")
#define CP_ASYNC_WAIT0()  asm volatile("cp.async.wait_group 0;" ::: "memory")

__device__ __forceinline__ void mma16816(float* c, uint32_t a0, uint32_t a1, uint32_t a2, uint32_t a3,
                                         uint32_t b0, uint32_t b1) {
    asm volatile("mma.sync.aligned.m16n8k16.row.col.f32.bf16.bf16.f32 "
        "{%0,%1,%2,%3}, {%4,%5,%6,%7}, {%8,%9}, {%0,%1,%2,%3};"
        : "+f"(c[0]), "+f"(c[1]), "+f"(c[2]), "+f"(c[3])
        : "r"(a0), "r"(a1), "r"(a2), "r"(a3), "r"(b0), "r"(b1));
}

// ---------------- prep ----------------
__global__ void prep_kernel(const float* __restrict__ Whh_f, const float* __restrict__ Whh_b,
                            const float* __restrict__ Wih_f, const float* __restrict__ Wih_b,
                            const float* __restrict__ bih_f, const float* __restrict__ bih_b,
                            const float* __restrict__ bhh_f, const float* __restrict__ bhh_b,
                            const float* __restrict__ W2) {
    int i = blockIdx.x*256 + threadIdx.x;
    if (i < 4*3*64*256) {
        // layout [dc][g][kk][t]: dc = d*2 + cta, t = kh*128 + tl, unit u = c*128 + tl
        int dc   = i / 49152;
        int rem  = i - dc*49152;
        int g    = rem / 16384;
        int rem2 = rem - g*16384;
        int kk   = rem2 >> 8;
        int t    = rem2 & 255;
        int d = dc >> 1, c = dc & 1;
        int u  = c*128 + (t & 127);
        int kh = t >> 7;
        int row = g*256 + u;
        int col = kh*128 + 2*kk;
        const float* W = d ? Whh_b : Whh_f;
        g_whh16[i] = __floats2half2_rn(W[row*HDIM + col], W[row*HDIM + col + 1]);
    }
    if (i < HDIM*NCOL) {
        int k = i / NCOL; int col = i - k*NCOL;
        int d = col / G3; int rc = col - d*G3;
        const float* W = d ? Wih_b : Wih_f;
        g_Bmat[i] = W[rc*HDIM + k];
    }
    if (i < K2*HDIM) {
        int kk = i >> 8; int c2 = i & 255;
        g_W2T[i] = W2[c2*K2 + kk];
    }
    if (i < NCOL) {
        int d = i / G3; int rc = i - d*G3;
        const float* bi = d ? bih_b : bih_f;
        const float* bh = d ? bhh_b : bhh_f;
        float v = bi[rc];
        if (rc < 512) v += bh[rc];
        g_beta[i] = v;
    }
    if (i < 2*HDIM) {
        int d = i >> 8; int j = i & 255;
        const float* bh = d ? bhh_b : bhh_f;
        g_bhhn[i] = bh[512 + j];
    }
}

// ---------------- conv1 ----------------
__global__ void __launch_bounds__(256) conv1_kernel(const float* __restrict__ X,
                                                    const float* __restrict__ W1,
                                                    const float* __restrict__ b1) {
    __shared__ float Ws[C1*39];
    __shared__ float Xs[CIN*516];
    int n = blockIdx.x, lt = blockIdx.y, tid = threadIdx.x;
    int l0 = lt*512;
    for (int i = tid; i < C1*39; i += 256) Ws[i] = W1[i];
    for (int i = tid; i < CIN*514; i += 256) {
        int ci = i / 514, off = i - ci*514;
        int g = l0 + off;
        Xs[ci*516 + off] = (g < LIN) ? X[(size_t)(n*CIN + ci)*LIN + g] : 0.f;
    }
    __syncthreads();
    float xa[CIN][3], xb[CIN][3];
    #pragma unroll
    for (int ci = 0; ci < CIN; ci++)
        #pragma unroll
        for (int k = 0; k < 3; k++) {
            xa[ci][k] = Xs[ci*516 + tid + k];
            xb[ci][k] = Xs[ci*516 + tid + 256 + k];
        }
    int l = l0 + tid;
    for (int co = 0; co < C1; co++) {
        float b = __ldg(b1 + co);
        float s0 = b, s1 = b;
        #pragma unroll
        for (int ci = 0; ci < CIN; ci++)
            #pragma unroll
            for (int k = 0; k < 3; k++) {
                float w = Ws[co*39 + ci*3 + k];
                s0 += xa[ci][k]*w;
                s1 += xb[ci][k]*w;
            }
        float* dst = g_conv1 + (size_t)(n*C1 + co)*L1OUT;
        if (l < L1OUT)       dst[l]       = s0;
        if (l + 256 < L1OUT) dst[l + 256] = s1;
    }
}

// ---------------- Cmat = W2T(384x256) . Bmat(256x1536) ----------------
__global__ void __launch_bounds__(256) cmat_kernel(void) {
    __shared__ float As[8][128];
    __shared__ float Bs[8][128];
    int tid = threadIdx.x;
    int tx = tid & 15, ty = tid >> 4;
    int n0 = blockIdx.x * 128, m0 = blockIdx.y * 128;
    float acc[8][8];
    #pragma unroll
    for (int i = 0; i < 8; i++)
        #pragma unroll
        for (int j = 0; j < 8; j++) acc[i][j] = 0.f;
    int arow = tid >> 1, acol = (tid & 1)*4;
    int brow = tid >> 5, bcol = (tid & 31)*4;
    for (int k0 = 0; k0 < HDIM; k0 += 8) {
        float4 av = *(const float4*)&g_W2T[(size_t)(m0 + arow)*HDIM + k0 + acol];
        As[acol+0][arow] = av.x; As[acol+1][arow] = av.y;
        As[acol+2][arow] = av.z; As[acol+3][arow] = av.w;
        *(float4*)&Bs[brow][bcol] = *(const float4*)&g_Bmat[(size_t)(k0 + brow)*NCOL + n0 + bcol];
        __syncthreads();
        #pragma unroll
        for (int k = 0; k < 8; k++) {
            float a[8], b[8];
            *(float4*)&a[0] = *(const float4*)&As[k][ty*4];
            *(float4*)&a[4] = *(const float4*)&As[k][64 + ty*4];
            *(float4*)&b[0] = *(const float4*)&Bs[k][tx*4];
            *(float4*)&b[4] = *(const float4*)&Bs[k][64 + tx*4];
            #pragma unroll
            for (int i = 0; i < 8; i++)
                #pragma unroll
                for (int j = 0; j < 8; j++) acc[i][j] += a[i]*b[j];
        }
        __syncthreads();
    }
    #pragma unroll
    for (int i = 0; i < 8; i++) {
        int mr = m0 + ((i < 4) ? ty*4 + i : 64 + ty*4 + i - 4);
        float* crow = g_Cmat + (size_t)mr*NCOL + n0;
        float4 v0, v1;
        v0.x=acc[i][0]; v0.y=acc[i][1]; v0.z=acc[i][2]; v0.w=acc[i][3];
        v1.x=acc[i][4]; v1.y=acc[i][5]; v1.z=acc[i][6]; v1.w=acc[i][7];
        *(float4*)&crow[tx*4]      = v0;
        *(float4*)&crow[64 + tx*4] = v1;
    }
}

// ---------------- Cmat -> bf16 hi/lo, transposed to [col][k] ----------------
__global__ void cconv_kernel(void) {
    int idx = blockIdx.x*256 + threadIdx.x;
    if (idx < NCOL*K2) {
        int col = idx / K2, k = idx - col*K2;
        float v = g_Cmat[(size_t)k*NCOL + col];
        __nv_bfloat16 hi = __float2bfloat16(v);
        float lo = v - __bfloat162float(hi);
        g_Ch[idx] = hi;
        g_Cl[idx] = __float2bfloat16(lo);
    }
}

// ---------------- beta2 ----------------
__global__ void beta2_kernel(const float* __restrict__ b2) {
    int col = blockIdx.x*256 + threadIdx.x;
    if (col >= NCOL) return;
    float s = g_beta[col];
    for (int k = 0; k < HDIM; k++)
        s += __ldg(b2 + k) * g_Bmat[(size_t)k*NCOL + col];
    g_beta2[col] = s;
}

// ---------------- materialize A (im2col) as bf16 hi/lo --------------------
__global__ void __launch_bounds__(256) amat_kernel(void) {
    int group = blockIdx.x;                 // 12288 blocks
    int c16 = group % 48;
    int m = (group / 48) * 256 + threadIdx.x;
    __nv_bfloat16 hi[8], lo[8];
    if (m < M_GI) {
        int nn = m / LSEQ;
        int l2 = m - nn*LSEQ;
        const float* base = g_conv1 + (size_t)nn*C1*L1OUT + 2*l2;
        #pragma unroll
        for (int j = 0; j < 8; j++) {
            int kk = c16*8 + j;
            int ci = kk / 3, kw = kk - ci*3;
            float v = base[(size_t)ci*L1OUT + kw];
            hi[j] = __float2bfloat16(v);
            lo[j] = __float2bfloat16(v - __bfloat162float(hi[j]));
        }
    } else {
        #pragma unroll
        for (int j = 0; j < 8; j++) { hi[j] = __float2bfloat16(0.f); lo[j] = hi[j]; }
    }
    size_t off = (size_t)m*K2 + c16*8;
    *(uint4*)&g_Ah[off] = *(uint4*)hi;
    *(uint4*)&g_Al[off] = *(uint4*)lo;
}

// ---------------- mma.sync GEMM: gi = A(bf16 hi/lo) . C^T(bf16 hi/lo) + beta2 -------
#define GEMM_SMEM (2*4*16384)

__device__ __forceinline__ void fill_tiles(uint32_t dst_base, int m0, int n0, int k0, int tid) {
    const __nv_bfloat16* srcs[4];
    srcs[0] = g_Ah + (size_t)m0*K2 + k0;
    srcs[1] = g_Al + (size_t)m0*K2 + k0;
    srcs[2] = g_Ch + (size_t)n0*K2 + k0;
    srcs[3] = g_Cl + (size_t)n0*K2 + k0;
    #pragma unroll
    for (int mat = 0; mat < 4; mat++) {
        const char* s = (const char*)srcs[mat];
        uint32_t d = dst_base + mat*16384;
        #pragma unroll
        for (int i = 0; i < 4; i++) {
            int idx = tid + i*256;
            int row = idx >> 3, ch = idx & 7;
            uint32_t so = (uint32_t)row*128 + (uint32_t)((ch*16) ^ ((row & 7) << 4));
            CP_ASYNC16(d + so, s + (size_t)row*(K2*2) + ch*16);
        }
    }
}

__global__ void __launch_bounds__(256, 1) tc_gemm_kernel(void) {
    extern __shared__ __align__(16) char sm[];
    uint32_t sb = smem_u32(sm);
    int tid = threadIdx.x;
    int lane = tid & 31, wid = tid >> 5;
    int wm = wid & 1, wn = wid >> 1;          // warp tile 64(m) x 32(n)
    int n0 = blockIdx.x * 128, m0 = blockIdx.y * 128;

    float acc[4][4][4];
    #pragma unroll
    for (int i = 0; i < 4; i++)
        #pragma unroll
        for (int j = 0; j < 4; j++)
            #pragma unroll
            for (int q = 0; q < 4; q++) acc[i][j][q] = 0.f;

    int q = lane >> 3, rr = lane & 7;
    int a_row = wm*64 + (q & 1)*8 + rr;
    int a_cq  = (q >> 1)*16;
    int b_row = wn*32 + (q >> 1)*8 + rr;
    int b_cq  = (q & 1)*16;
    uint32_t a_xor = (uint32_t)(rr << 4);
    uint32_t b_xor = (uint32_t)(rr << 4);

    fill_tiles(sb, m0, n0, 0, tid);
    CP_ASYNC_COMMIT();

    #pragma unroll 1
    for (int c = 0; c < 6; c++) {
        CP_ASYNC_WAIT0();
        __syncthreads();
        if (c < 5) {
            fill_tiles(sb + ((c + 1) & 1)*65536, m0, n0, (c + 1)*64, tid);
            CP_ASYNC_COMMIT();
        }
        uint32_t tb = sb + (c & 1)*65536;
        #pragma unroll
        for (int kf = 0; kf < 4; kf++) {
            uint32_t Ah_f[4][4], Al_f[4][4], Bh_f[2][4], Bl_f[2][4];
            uint32_t acol = (uint32_t)((a_cq + kf*32) ^ a_xor);
            uint32_t bcol = (uint32_t)((b_cq + kf*32) ^ b_xor);
            #pragma unroll
            for (int mf = 0; mf < 4; mf++) {
                uint32_t off = (uint32_t)(a_row + mf*16)*128 + acol;
                asm volatile("ldmatrix.sync.aligned.m8n8.x4.shared.b16 {%0,%1,%2,%3}, [%4];"
                    : "=r"(Ah_f[mf][0]), "=r"(Ah_f[mf][1]), "=r"(Ah_f[mf][2]), "=r"(Ah_f[mf][3])
                    : "r"(tb + off));
                asm volatile("ldmatrix.sync.aligned.m8n8.x4.shared.b16 {%0,%1,%2,%3}, [%4];"
                    : "=r"(Al_f[mf][0]), "=r"(Al_f[mf][1]), "=r"(Al_f[mf][2]), "=r"(Al_f[mf][3])
                    : "r"(tb + 16384 + off));
            }
            #pragma unroll
            for (int nfp = 0; nfp < 2; nfp++) {
                uint32_t off = (uint32_t)(b_row + nfp*16)*128 + bcol;
                asm volatile("ldmatrix.sync.aligned.m8n8.x4.shared.b16 {%0,%1,%2,%3}, [%4];"
                    : "=r"(Bh_f[nfp][0]), "=r"(Bh_f[nfp][1]), "=r"(Bh_f[nfp][2]), "=r"(Bh_f[nfp][3])
                    : "r"(tb + 32768 + off));
                asm volatile("ldmatrix.sync.aligned.m8n8.x4.shared.b16 {%0,%1,%2,%3}, [%4];"
                    : "=r"(Bl_f[nfp][0]), "=r"(Bl_f[nfp][1]), "=r"(Bl_f[nfp][2]), "=r"(Bl_f[nfp][3])
                    : "r"(tb + 49152 + off));
            }
            #pragma unroll
            for (int mf = 0; mf < 4; mf++)
                #pragma unroll
                for (int nf = 0; nf < 4; nf++) {
                    int nfp = nf >> 1, sel = (nf & 1)*2;
                    mma16816(acc[mf][nf], Ah_f[mf][0], Ah_f[mf][1], Ah_f[mf][2], Ah_f[mf][3],
                             Bh_f[nfp][sel], Bh_f[nfp][sel+1]);
                    mma16816(acc[mf][nf], Ah_f[mf][0], Ah_f[mf][1], Ah_f[mf][2], Ah_f[mf][3],
                             Bl_f[nfp][sel], Bl_f[nfp][sel+1]);
                    mma16816(acc[mf][nf], Al_f[mf][0], Al_f[mf][1], Al_f[mf][2], Al_f[mf][3],
                             Bh_f[nfp][sel], Bh_f[nfp][sel+1]);
                }
        }
    }

    int col0 = n0 + wn*32 + (lane & 3)*2;
    int row0 = m0 + wm*64 + (lane >> 2);
    float2 bb[4];
    #pragma unroll
    for (int nf = 0; nf < 4; nf++)
        bb[nf] = *(const float2*)&g_beta2[col0 + nf*8];
    #pragma unroll
    for (int mf = 0; mf < 4; mf++) {
        int mr0 = row0 + mf*16;
        int mr1 = mr0 + 8;
        #pragma unroll
        for (int nf = 0; nf < 4; nf++) {
            int cc = col0 + nf*8;
            if (mr0 < M_GI) {
                float2 v; v.x = acc[mf][nf][0] + bb[nf].x; v.y = acc[mf][nf][1] + bb[nf].y;
                *(float2*)&g_gi[(size_t)mr0*NCOL + cc] = v;
            }
            if (mr1 < M_GI) {
                float2 v; v.x = acc[mf][nf][2] + bb[nf].x; v.y = acc[mf][nf][3] + bb[nf].y;
                *(float2*)&g_gi[(size_t)mr1*NCOL + cc] = v;
            }
        }
    }
}

// ---------------- GRU: unit-split cluster, intra-CTA reduction, pipelined h push ----
__global__ void __cluster_dims__(2,1,1) __launch_bounds__(256,1)
gru_kernel(void) {
    __shared__ __align__(16) __half hh_loc[128];       // this CTA's h half
    __shared__ __align__(16) __half hh_rem[2][128];    // peer's h half, double-buffered
    __shared__ float partials[384];
    __shared__ __align__(8) uint64_t step_mbar;

    int tid = threadIdx.x;
    uint32_t rank;
    asm("mov.u32 %0, %%cluster_ctarank;" : "=r"(rank));
    int chain = blockIdx.x >> 1;
    int d = chain >> 5;
    int n = chain & 31;
    int c = (int)rank;
    int tl = tid & 127;          // local unit index
    int kh = tid >> 7;           // K-half this thread computes
    int u  = c*128 + tl;         // global hidden unit
    bool comb   = (kh == 0);     // combining thread (also K-half 0)
    bool rlocal = (kh == c);     // this thread's K-half reads the LOCAL h

    // weights: rows u, 256+u, 512+u over K-half kh (64 half2 each), coalesced by layout
    __half2 w0[64], w1[64], w2[64];
    {
        const __half2* base = g_whh16 + (size_t)(d*2 + c)*49152;
        #pragma unroll
        for (int kk = 0; kk < 64; kk++) {
            w0[kk] = base[kk*256 + tid];
            w1[kk] = base[16384 + kk*256 + tid];
            w2[kk] = base[32768 + kk*256 + tid];
        }
    }
    if (tid < 128) {
        hh_loc[tid]    = __float2half_rn(0.f);
        hh_rem[0][tid] = __float2half_rn(0.f);
        hh_rem[1][tid] = __float2half_rn(0.f);
    }
    uint32_t mbar_u = smem_u32(&step_mbar);
    if (tid == 0) MBARRIER_INIT(mbar_u, 1);

    float bn = comb ? g_bhhn[d*HDIM + u] : 0.f;
    float* gout = d ? g_outb : g_outf;
    float h_reg = 0.f;

    uint32_t rem_u = smem_u32(hh_rem);
    uint32_t peer_rem = 0, peer_mbar = 0;
    asm("mapa.shared::cluster.u32 %0, %1, %2;" : "=r"(peer_rem)  : "r"(rem_u),  "r"(rank ^ 1u));
    asm("mapa.shared::cluster.u32 %0, %1, %2;" : "=r"(peer_mbar) : "r"(mbar_u), "r"(rank ^ 1u));
    __syncthreads();
    asm volatile("barrier.cluster.arrive.aligned;" ::: "memory");
    asm volatile("barrier.cluster.wait.aligned;"   ::: "memory");

    const uint4* hv_loc = (const uint4*)hh_loc;
    const uint4* hv_rem = (const uint4*)hh_rem;

    for (int s = 0; s < LSEQ; s++) {
        int tpos = d ? (LSEQ - 1 - s) : s;
        float gir = 0.f, giz = 0.f, gin = 0.f;
        if (comb) {
            size_t gbase = ((size_t)(n*LSEQ + tpos))*NCOL + (size_t)d*G3 + u;
            gir = __ldg(&g_gi[gbase]);
            giz = __ldg(&g_gi[gbase + 256]);
            gin = __ldg(&g_gi[gbase + 512]);
        }
        if (!rlocal && s)
            MBARRIER_WAIT_PARITY_CL(mbar_u, (s + 1) & 1);
        const uint4* hv4 = rlocal ? hv_loc : (hv_rem + (s & 1)*16);

        float a0 = 0.f, a1 = 0.f, a2 = 0.f;
        #pragma unroll
        for (int g2 = 0; g2 < 2; g2++) {
            __half2 zz = __float2half2_rn(0.f);
            __half2 p00=zz,p01=zz,p10=zz,p11=zz,p20=zz,p21=zz;
            #pragma unroll
            for (int uu = 0; uu < 8; uu++) {
                uint4 hv = hv4[g2*8 + uu];
                __half2 ha = *(__half2*)&hv.x;
                __half2 hb = *(__half2*)&hv.y;
                __half2 hc = *(__half2*)&hv.z;
                __half2 hd = *(__half2*)&hv.w;
                int kb = g2*32 + uu*4;
                p00 = __hfma2(w0[kb+0], ha, p00);
                p01 = __hfma2(w0[kb+1], hb, p01);
                p00 = __hfma2(w0[kb+2], hc, p00);
                p01 = __hfma2(w0[kb+3], hd, p01);
                p10 = __hfma2(w1[kb+0], ha, p10);
                p11 = __hfma2(w1[kb+1], hb, p11);
                p10 = __hfma2(w1[kb+2], hc, p10);
                p11 = __hfma2(w1[kb+3], hd, p11);
                p20 = __hfma2(w2[kb+0], ha, p20);
                p21 = __hfma2(w2[kb+1], hb, p21);
                p20 = __hfma2(w2[kb+2], hc, p20);
                p21 = __hfma2(w2[kb+3], hd, p21);
            }
            float2 f;
            f = __half22float2(__hadd2(p00, p01)); a0 += f.x + f.y;
            f = __half22float2(__hadd2(p10, p11)); a1 += f.x + f.y;
            f = __half22float2(__hadd2(p20, p21)); a2 += f.x + f.y;
        }

        if (!comb) {
            partials[tl]       = a0;
            partials[128 + tl] = a1;
            partials[256 + tl] = a2;
        }
        __syncthreads();
        if (comb) {
            float ghr = a0 + partials[tl];
            float ghz = a1 + partials[128 + tl];
            float ghn = a2 + partials[256 + tl];
            float r = 1.f/(1.f + __expf(-(gir + ghr)));
            float z = 1.f/(1.f + __expf(-(giz + ghz)));
            float nn2 = tanhf(gin + r*(ghn + bn));
            h_reg = (1.f - z)*nn2 + z*h_reg;
            gout[((size_t)(n*LSEQ + tpos))*HDIM + u] = h_reg;
            hh_loc[tl] = __float2half_rn(h_reg);
        }
        __syncthreads();
        // publish our h half to peer's buffer for step s+1 (off critical path)
        if (tid < 32) {
            if (tid < 16) {
                uint4 v = ((const uint4*)hh_loc)[tid];
                uint32_t dst = peer_rem + (uint32_t)(((s + 1) & 1)*256 + tid*16);
                asm volatile("st.shared::cluster.v4.b32 [%0], {%1,%2,%3,%4};"
                    :: "r"(dst), "r"(v.x), "r"(v.y), "r"(v.z), "r"(v.w) : "memory");
            }
            __syncwarp();
            if (tid == 0) {
                asm volatile("fence.acq_rel.cluster;" ::: "memory");
                asm volatile("mbarrier.arrive.release.cluster.shared::cluster.b64 _, [%0];"
                    :: "r"(peer_mbar) : "memory");
            }
        }
    }
    asm volatile("barrier.cluster.arrive.aligned;" ::: "memory");
    asm volatile("barrier.cluster.wait.aligned;"   ::: "memory");
}

// ---------------- combine + hidden_last ----------------
__global__ void __launch_bounds__(256) combine_kernel(float* __restrict__ out) {
    int idx = blockIdx.x*256 + threadIdx.x;
    const int comb = LSEQ*NB*HDIM;
    if (idx < comb) {
        int c = idx & 255;
        int rem = idx >> 8;
        int nn = rem & 31;
        int l = rem >> 5;
        size_t base = ((size_t)(nn*LSEQ + l)) << 8;
        float f = g_outf[base + c];
        float b = g_outb[base + (255 - c)];
        float v = 0.5f*(f + b);
        out[idx] = v > 0.f ? v : 0.f;
    } else if (idx < comb + NB*HDIM) {
        int i2 = idx - comb;
        int nn = i2 >> 8, c = i2 & 255;
        out[idx] = g_outb[((size_t)(nn*LSEQ)) * HDIM + c];
    }
}

// ---------------- launch ----------------
extern "C" void kernel_launch(void* const* d_in, const int* in_sizes, int n_in,
                              void* d_out, int out_size) {
    const float* X     = (const float*)d_in[0];
    const float* W1    = (const float*)d_in[1];
    const float* b1    = (const float*)d_in[2];
    const float* W2    = (const float*)d_in[3];
    const float* b2    = (const float*)d_in[4];
    const float* Wih_f = (const float*)d_in[5];
    const float* Whh_f = (const float*)d_in[6];
    const float* bih_f = (const float*)d_in[7];
    const float* bhh_f = (const float*)d_in[8];
    const float* Wih_b = (const float*)d_in[9];
    const float* Whh_b = (const float*)d_in[10];
    const float* bih_b = (const float*)d_in[11];
    const float* bhh_b = (const float*)d_in[12];
    float* out = (float*)d_out;

    cudaFuncSetAttribute(tc_gemm_kernel, cudaFuncAttributeMaxDynamicSharedMemorySize, GEMM_SMEM);

    prep_kernel<<<1536, 256>>>(Whh_f, Whh_b, Wih_f, Wih_b, bih_f, bih_b, bhh_f, bhh_b, W2);
    conv1_kernel<<<dim3(NB, 8), 256>>>(X, W1, b1);
    cmat_kernel<<<dim3(12, 3), 256>>>();
    cconv_kernel<<<(NCOL*K2 + 255)/256, 256>>>();
    beta2_kernel<<<6, 256>>>(b2);
    amat_kernel<<<12288, 256>>>();
    tc_gemm_kernel<<<dim3(12, 512), 256, GEMM_SMEM>>>();
    gru_kernel<<<128, 256>>>();
    int total = LSEQ*NB*HDIM + NB*HDIM;
    combine_kernel<<<(total + 255)/256, 256>>>(out);
}

// round 12
// speedup vs baseline: 1.5502x; 1.1533x over previous
#include <cuda_runtime.h>
#include <cuda_fp16.h>
#include <cuda_bf16.h>
#include <cstdint>
#include <cstddef>

#define NB    32
#define CIN   13
#define LIN   4096
#define C1    128
#define L1OUT 4094
#define HDIM  256
#define LSEQ  2046
#define G3    768
#define M_GI  (LSEQ*NB)      /* 65472 */
#define M_PAD 65536
#define NCOL  1536
#define K2    384

// ---------------- static device scratch ----------------
__device__ float  g_conv1[(size_t)NB*C1*L1OUT];
__device__ float  g_gi[(size_t)M_GI*NCOL];
__device__ float  g_outf[(size_t)M_GI*HDIM];
__device__ float  g_outb[(size_t)M_GI*HDIM];
__device__ __align__(16) __half2 g_whh16[4*64*G3];           // [dr][kk][row]
__device__ float  g_Bmat[HDIM*NCOL];
__device__ float  g_W2T[K2*HDIM];
__device__ float  g_Cmat[(size_t)K2*NCOL];                   // [k][col]
__device__ __align__(16) __nv_bfloat16 g_Ah[(size_t)M_PAD*K2];
__device__ __align__(16) __nv_bfloat16 g_Al[(size_t)M_PAD*K2];
__device__ __align__(16) __nv_bfloat16 g_Ch[(size_t)NCOL*K2];    // [col][k]
__device__ __align__(16) __nv_bfloat16 g_Cl[(size_t)NCOL*K2];
__device__ float  g_beta[NCOL];
__device__ float  g_beta2[NCOL];
__device__ float  g_bhhn[2*HDIM];

// ---------------- ptx helpers ----------------
__device__ __forceinline__ uint32_t smem_u32(const void* p) {
    uint32_t a;
    asm("{ .reg .u64 t; cvta.to.shared.u64 t, %1; cvt.u32.u64 %0, t; }" : "=r"(a) : "l"(p));
    return a;
}
#define CP_ASYNC16(dst, src) \
    asm volatile("cp.async.cg.shared.global [%0], [%1], 16;" :: "r"(dst), "l"(src) : "memory")
#define CP_ASYNC_COMMIT() asm volatile("cp.async.commit_group;" ::: "memory")
#define CP_ASYNC_WAIT0()  asm volatile("cp.async.wait_group 0;" ::: "memory")

__device__ __forceinline__ void mma16816(float* c, uint32_t a0, uint32_t a1, uint32_t a2, uint32_t a3,
                                         uint32_t b0, uint32_t b1) {
    asm volatile("mma.sync.aligned.m16n8k16.row.col.f32.bf16.bf16.f32 "
        "{%0,%1,%2,%3}, {%4,%5,%6,%7}, {%8,%9}, {%0,%1,%2,%3};"
        : "+f"(c[0]), "+f"(c[1]), "+f"(c[2]), "+f"(c[3])
        : "r"(a0), "r"(a1), "r"(a2), "r"(a3), "r"(b0), "r"(b1));
}

// ---------------- prep ----------------
__global__ void prep_kernel(const float* __restrict__ Whh_f, const float* __restrict__ Whh_b,
                            const float* __restrict__ Wih_f, const float* __restrict__ Wih_b,
                            const float* __restrict__ bih_f, const float* __restrict__ bih_b,
                            const float* __restrict__ bhh_f, const float* __restrict__ bhh_b,
                            const float* __restrict__ W2) {
    int i = blockIdx.x*256 + threadIdx.x;
    if (i < 4*64*G3) {
        int dr  = i / (64*G3);
        int rem = i - dr*(64*G3);
        int kk  = rem / G3;
        int row = rem - kk*G3;
        int d = dr >> 1, r = dr & 1;
        const float* W = d ? Whh_b : Whh_f;
        int c = r*128 + 2*kk;
        g_whh16[i] = __floats2half2_rn(W[row*HDIM + c], W[row*HDIM + c + 1]);
    }
    if (i < HDIM*NCOL) {
        int k = i / NCOL; int col = i - k*NCOL;
        int d = col / G3; int rc = col - d*G3;
        const float* W = d ? Wih_b : Wih_f;
        g_Bmat[i] = W[rc*HDIM + k];
    }
    if (i < K2*HDIM) {
        int kk = i >> 8; int c2 = i & 255;
        g_W2T[i] = W2[c2*K2 + kk];
    }
    if (i < NCOL) {
        int d = i / G3; int rc = i - d*G3;
        const float* bi = d ? bih_b : bih_f;
        const float* bh = d ? bhh_b : bhh_f;
        float v = bi[rc];
        if (rc < 512) v += bh[rc];
        g_beta[i] = v;
    }
    if (i < 2*HDIM) {
        int d = i >> 8; int j = i & 255;
        const float* bh = d ? bhh_b : bhh_f;
        g_bhhn[i] = bh[512 + j];
    }
}

// ---------------- conv1 ----------------
__global__ void __launch_bounds__(256) conv1_kernel(const float* __restrict__ X,
                                                    const float* __restrict__ W1,
                                                    const float* __restrict__ b1) {
    __shared__ float Ws[C1*39];
    __shared__ float Xs[CIN*516];
    int n = blockIdx.x, lt = blockIdx.y, tid = threadIdx.x;
    int l0 = lt*512;
    for (int i = tid; i < C1*39; i += 256) Ws[i] = W1[i];
    for (int i = tid; i < CIN*514; i += 256) {
        int ci = i / 514, off = i - ci*514;
        int g = l0 + off;
        Xs[ci*516 + off] = (g < LIN) ? X[(size_t)(n*CIN + ci)*LIN + g] : 0.f;
    }
    __syncthreads();
    float xa[CIN][3], xb[CIN][3];
    #pragma unroll
    for (int ci = 0; ci < CIN; ci++)
        #pragma unroll
        for (int k = 0; k < 3; k++) {
            xa[ci][k] = Xs[ci*516 + tid + k];
            xb[ci][k] = Xs[ci*516 + tid + 256 + k];
        }
    int l = l0 + tid;
    for (int co = 0; co < C1; co++) {
        float b = __ldg(b1 + co);
        float s0 = b, s1 = b;
        #pragma unroll
        for (int ci = 0; ci < CIN; ci++)
            #pragma unroll
            for (int k = 0; k < 3; k++) {
                float w = Ws[co*39 + ci*3 + k];
                s0 += xa[ci][k]*w;
                s1 += xb[ci][k]*w;
            }
        float* dst = g_conv1 + (size_t)(n*C1 + co)*L1OUT;
        if (l < L1OUT)       dst[l]       = s0;
        if (l + 256 < L1OUT) dst[l + 256] = s1;
    }
}

// ---------------- Cmat = W2T(384x256) . Bmat(256x1536) ----------------
__global__ void __launch_bounds__(256) cmat_kernel(void) {
    __shared__ float As[8][128];
    __shared__ float Bs[8][128];
    int tid = threadIdx.x;
    int tx = tid & 15, ty = tid >> 4;
    int n0 = blockIdx.x * 128, m0 = blockIdx.y * 128;
    float acc[8][8];
    #pragma unroll
    for (int i = 0; i < 8; i++)
        #pragma unroll
        for (int j = 0; j < 8; j++) acc[i][j] = 0.f;
    int arow = tid >> 1, acol = (tid & 1)*4;
    int brow = tid >> 5, bcol = (tid & 31)*4;
    for (int k0 = 0; k0 < HDIM; k0 += 8) {
        float4 av = *(const float4*)&g_W2T[(size_t)(m0 + arow)*HDIM + k0 + acol];
        As[acol+0][arow] = av.x; As[acol+1][arow] = av.y;
        As[acol+2][arow] = av.z; As[acol+3][arow] = av.w;
        *(float4*)&Bs[brow][bcol] = *(const float4*)&g_Bmat[(size_t)(k0 + brow)*NCOL + n0 + bcol];
        __syncthreads();
        #pragma unroll
        for (int k = 0; k < 8; k++) {
            float a[8], b[8];
            *(float4*)&a[0] = *(const float4*)&As[k][ty*4];
            *(float4*)&a[4] = *(const float4*)&As[k][64 + ty*4];
            *(float4*)&b[0] = *(const float4*)&Bs[k][tx*4];
            *(float4*)&b[4] = *(const float4*)&Bs[k][64 + tx*4];
            #pragma unroll
            for (int i = 0; i < 8; i++)
                #pragma unroll
                for (int j = 0; j < 8; j++) acc[i][j] += a[i]*b[j];
        }
        __syncthreads();
    }
    #pragma unroll
    for (int i = 0; i < 8; i++) {
        int mr = m0 + ((i < 4) ? ty*4 + i : 64 + ty*4 + i - 4);
        float* crow = g_Cmat + (size_t)mr*NCOL + n0;
        float4 v0, v1;
        v0.x=acc[i][0]; v0.y=acc[i][1]; v0.z=acc[i][2]; v0.w=acc[i][3];
        v1.x=acc[i][4]; v1.y=acc[i][5]; v1.z=acc[i][6]; v1.w=acc[i][7];
        *(float4*)&crow[tx*4]      = v0;
        *(float4*)&crow[64 + tx*4] = v1;
    }
}

// ---------------- Cmat -> bf16 hi/lo, transposed to [col][k] ----------------
__global__ void cconv_kernel(void) {
    int idx = blockIdx.x*256 + threadIdx.x;
    if (idx < NCOL*K2) {
        int col = idx / K2, k = idx - col*K2;
        float v = g_Cmat[(size_t)k*NCOL + col];
        __nv_bfloat16 hi = __float2bfloat16(v);
        float lo = v - __bfloat162float(hi);
        g_Ch[idx] = hi;
        g_Cl[idx] = __float2bfloat16(lo);
    }
}

// ---------------- beta2 (parallel tree-reduce: 16 lanes per column) ----------------
__global__ void beta2_kernel(const float* __restrict__ b2) {
    int col = blockIdx.x*16 + (threadIdx.x >> 4);
    int l16 = threadIdx.x & 15;
    float s = 0.f;
    for (int k = l16; k < HDIM; k += 16)
        s += __ldg(b2 + k) * g_Bmat[(size_t)k*NCOL + col];
    #pragma unroll
    for (int o = 8; o; o >>= 1)
        s += __shfl_down_sync(0xffffffffu, s, o, 16);
    if (l16 == 0) g_beta2[col] = s + g_beta[col];
}

// ---------------- materialize A (im2col) as bf16 hi/lo --------------------
__global__ void __launch_bounds__(256) amat_kernel(void) {
    int group = blockIdx.x;                 // 12288 blocks
    int c16 = group % 48;
    int m = (group / 48) * 256 + threadIdx.x;
    __nv_bfloat16 hi[8], lo[8];
    if (m < M_GI) {
        int nn = m / LSEQ;
        int l2 = m - nn*LSEQ;
        const float* base = g_conv1 + (size_t)nn*C1*L1OUT + 2*l2;
        #pragma unroll
        for (int j = 0; j < 8; j++) {
            int kk = c16*8 + j;
            int ci = kk / 3, kw = kk - ci*3;
            float v = base[(size_t)ci*L1OUT + kw];
            hi[j] = __float2bfloat16(v);
            lo[j] = __float2bfloat16(v - __bfloat162float(hi[j]));
        }
    } else {
        #pragma unroll
        for (int j = 0; j < 8; j++) { hi[j] = __float2bfloat16(0.f); lo[j] = hi[j]; }
    }
    size_t off = (size_t)m*K2 + c16*8;
    *(uint4*)&g_Ah[off] = *(uint4*)hi;
    *(uint4*)&g_Al[off] = *(uint4*)lo;
}

// ---------------- mma.sync GEMM: gi = A(bf16 hi/lo) . C^T(bf16 hi/lo) + beta2 -------
#define GEMM_SMEM (2*4*16384)

__device__ __forceinline__ void fill_tiles(uint32_t dst_base, int m0, int n0, int k0, int tid) {
    const __nv_bfloat16* srcs[4];
    srcs[0] = g_Ah + (size_t)m0*K2 + k0;
    srcs[1] = g_Al + (size_t)m0*K2 + k0;
    srcs[2] = g_Ch + (size_t)n0*K2 + k0;
    srcs[3] = g_Cl + (size_t)n0*K2 + k0;
    #pragma unroll
    for (int mat = 0; mat < 4; mat++) {
        const char* s = (const char*)srcs[mat];
        uint32_t d = dst_base + mat*16384;
        #pragma unroll
        for (int i = 0; i < 4; i++) {
            int idx = tid + i*256;
            int row = idx >> 3, ch = idx & 7;
            uint32_t so = (uint32_t)row*128 + (uint32_t)((ch*16) ^ ((row & 7) << 4));
            CP_ASYNC16(d + so, s + (size_t)row*(K2*2) + ch*16);
        }
    }
}

__global__ void __launch_bounds__(256, 1) tc_gemm_kernel(void) {
    extern __shared__ __align__(16) char sm[];
    uint32_t sb = smem_u32(sm);
    int tid = threadIdx.x;
    int lane = tid & 31, wid = tid >> 5;
    int wm = wid & 1, wn = wid >> 1;          // warp tile 64(m) x 32(n)
    int n0 = blockIdx.x * 128, m0 = blockIdx.y * 128;

    float acc[4][4][4];
    #pragma unroll
    for (int i = 0; i < 4; i++)
        #pragma unroll
        for (int j = 0; j < 4; j++)
            #pragma unroll
            for (int q = 0; q < 4; q++) acc[i][j][q] = 0.f;

    int q = lane >> 3, rr = lane & 7;
    int a_row = wm*64 + (q & 1)*8 + rr;
    int a_cq  = (q >> 1)*16;
    int b_row = wn*32 + (q >> 1)*8 + rr;
    int b_cq  = (q & 1)*16;
    uint32_t a_xor = (uint32_t)(rr << 4);
    uint32_t b_xor = (uint32_t)(rr << 4);

    fill_tiles(sb, m0, n0, 0, tid);
    CP_ASYNC_COMMIT();

    #pragma unroll 1
    for (int c = 0; c < 6; c++) {
        CP_ASYNC_WAIT0();
        __syncthreads();
        if (c < 5) {
            fill_tiles(sb + ((c + 1) & 1)*65536, m0, n0, (c + 1)*64, tid);
            CP_ASYNC_COMMIT();
        }
        uint32_t tb = sb + (c & 1)*65536;
        #pragma unroll
        for (int kf = 0; kf < 4; kf++) {
            uint32_t Ah_f[4][4], Al_f[4][4], Bh_f[2][4], Bl_f[2][4];
            uint32_t acol = (uint32_t)((a_cq + kf*32) ^ a_xor);
            uint32_t bcol = (uint32_t)((b_cq + kf*32) ^ b_xor);
            #pragma unroll
            for (int mf = 0; mf < 4; mf++) {
                uint32_t off = (uint32_t)(a_row + mf*16)*128 + acol;
                asm volatile("ldmatrix.sync.aligned.m8n8.x4.shared.b16 {%0,%1,%2,%3}, [%4];"
                    : "=r"(Ah_f[mf][0]), "=r"(Ah_f[mf][1]), "=r"(Ah_f[mf][2]), "=r"(Ah_f[mf][3])
                    : "r"(tb + off));
                asm volatile("ldmatrix.sync.aligned.m8n8.x4.shared.b16 {%0,%1,%2,%3}, [%4];"
                    : "=r"(Al_f[mf][0]), "=r"(Al_f[mf][1]), "=r"(Al_f[mf][2]), "=r"(Al_f[mf][3])
                    : "r"(tb + 16384 + off));
            }
            #pragma unroll
            for (int nfp = 0; nfp < 2; nfp++) {
                uint32_t off = (uint32_t)(b_row + nfp*16)*128 + bcol;
                asm volatile("ldmatrix.sync.aligned.m8n8.x4.shared.b16 {%0,%1,%2,%3}, [%4];"
                    : "=r"(Bh_f[nfp][0]), "=r"(Bh_f[nfp][1]), "=r"(Bh_f[nfp][2]), "=r"(Bh_f[nfp][3])
                    : "r"(tb + 32768 + off));
                asm volatile("ldmatrix.sync.aligned.m8n8.x4.shared.b16 {%0,%1,%2,%3}, [%4];"
                    : "=r"(Bl_f[nfp][0]), "=r"(Bl_f[nfp][1]), "=r"(Bl_f[nfp][2]), "=r"(Bl_f[nfp][3])
                    : "r"(tb + 49152 + off));
            }
            #pragma unroll
            for (int mf = 0; mf < 4; mf++)
                #pragma unroll
                for (int nf = 0; nf < 4; nf++) {
                    int nfp = nf >> 1, sel = (nf & 1)*2;
                    mma16816(acc[mf][nf], Ah_f[mf][0], Ah_f[mf][1], Ah_f[mf][2], Ah_f[mf][3],
                             Bh_f[nfp][sel], Bh_f[nfp][sel+1]);
                    mma16816(acc[mf][nf], Ah_f[mf][0], Ah_f[mf][1], Ah_f[mf][2], Ah_f[mf][3],
                             Bl_f[nfp][sel], Bl_f[nfp][sel+1]);
                    mma16816(acc[mf][nf], Al_f[mf][0], Al_f[mf][1], Al_f[mf][2], Al_f[mf][3],
                             Bh_f[nfp][sel], Bh_f[nfp][sel+1]);
                }
        }
    }

    int col0 = n0 + wn*32 + (lane & 3)*2;
    int row0 = m0 + wm*64 + (lane >> 2);
    float2 bb[4];
    #pragma unroll
    for (int nf = 0; nf < 4; nf++)
        bb[nf] = *(const float2*)&g_beta2[col0 + nf*8];
    #pragma unroll
    for (int mf = 0; mf < 4; mf++) {
        int mr0 = row0 + mf*16;
        int mr1 = mr0 + 8;
        #pragma unroll
        for (int nf = 0; nf < 4; nf++) {
            int cc = col0 + nf*8;
            if (mr0 < M_GI) {
                float2 v; v.x = acc[mf][nf][0] + bb[nf].x; v.y = acc[mf][nf][1] + bb[nf].y;
                *(float2*)&g_gi[(size_t)mr0*NCOL + cc] = v;
            }
            if (mr1 < M_GI) {
                float2 v; v.x = acc[mf][nf][2] + bb[nf].x; v.y = acc[mf][nf][3] + bb[nf].y;
                *(float2*)&g_gi[(size_t)mr1*NCOL + cc] = v;
            }
        }
    }
}

// ---------------- GRU (R6 proven version: register weights + cluster.sync) ---------
__global__ void __cluster_dims__(2,1,1) __launch_bounds__(256,1)
gru_kernel(void) {
    __shared__ __align__(16) __half2 h2_s[64];
    __shared__ __align__(16) float recv[2*384];

    int tid = threadIdx.x;
    uint32_t rank;
    asm("mov.u32 %0, %%cluster_ctarank;" : "=r"(rank));
    int chain = blockIdx.x >> 1;
    int d = chain >> 5;
    int n = chain & 31;
    int dr = d*2 + (int)rank;

    __half2 w0[64], w1[64], w2[64];
    {
        const __half2* base = g_whh16 + (size_t)dr*64*G3;
        #pragma unroll
        for (int kk = 0; kk < 64; kk++) {
            w0[kk] = base[kk*G3 + tid];
            w1[kk] = base[kk*G3 + tid + 256];
            w2[kk] = base[kk*G3 + tid + 512];
        }
    }
    if (tid < 64) h2_s[tid] = __float2half2_rn(0.f);

    int jj = tid;
    bool own = ((jj >> 7) == (int)rank);
    int jloc = jj & 127;
    float bn = own ? g_bhhn[d*HDIM + jj] : 0.f;
    float* gout = d ? g_outb : g_outf;
    float h_reg = 0.f;
    __half* hh_s = (__half*)h2_s;

    uint32_t recv_u = smem_u32(recv);
    uint32_t pa0 = 0, pa1 = 0;
    {
        uint32_t a0 = recv_u + (uint32_t)jloc*4u;
        uint32_t a1 = recv_u + (384u + (uint32_t)jloc)*4u;
        asm("mapa.shared::cluster.u32 %0, %1, %2;" : "=r"(pa0) : "r"(a0), "r"(rank ^ 1u));
        asm("mapa.shared::cluster.u32 %0, %1, %2;" : "=r"(pa1) : "r"(a1), "r"(rank ^ 1u));
    }
    __syncthreads();

    const uint4* hv4 = (const uint4*)h2_s;

    for (int s = 0; s < LSEQ; s++) {
        int tpos = d ? (LSEQ - 1 - s) : s;
        size_t gbase = ((size_t)(n*LSEQ + tpos))*NCOL + (size_t)d*G3 + jj;
        float gir = 0.f, giz = 0.f, gin = 0.f;
        if (own) {
            gir = __ldg(&g_gi[gbase]);
            giz = __ldg(&g_gi[gbase + 256]);
            gin = __ldg(&g_gi[gbase + 512]);
        }

        float a0 = 0.f, a1 = 0.f, a2 = 0.f;
        #pragma unroll
        for (int g2 = 0; g2 < 2; g2++) {
            __half2 zz = __float2half2_rn(0.f);
            __half2 p00=zz,p01=zz,p10=zz,p11=zz,p20=zz,p21=zz;
            #pragma unroll
            for (int u = 0; u < 8; u++) {
                uint4 hv = hv4[g2*8 + u];
                __half2 ha = *(__half2*)&hv.x;
                __half2 hb = *(__half2*)&hv.y;
                __half2 hc = *(__half2*)&hv.z;
                __half2 hd = *(__half2*)&hv.w;
                int kb = g2*32 + u*4;
                p00 = __hfma2(w0[kb+0], ha, p00);
                p01 = __hfma2(w0[kb+1], hb, p01);
                p00 = __hfma2(w0[kb+2], hc, p00);
                p01 = __hfma2(w0[kb+3], hd, p01);
                p10 = __hfma2(w1[kb+0], ha, p10);
                p11 = __hfma2(w1[kb+1], hb, p11);
                p10 = __hfma2(w1[kb+2], hc, p10);
                p11 = __hfma2(w1[kb+3], hd, p11);
                p20 = __hfma2(w2[kb+0], ha, p20);
                p21 = __hfma2(w2[kb+1], hb, p21);
                p20 = __hfma2(w2[kb+2], hc, p20);
                p21 = __hfma2(w2[kb+3], hd, p21);
            }
            float2 f;
            f = __half22float2(__hadd2(p00, p01)); a0 += f.x + f.y;
            f = __half22float2(__hadd2(p10, p11)); a1 += f.x + f.y;
            f = __half22float2(__hadd2(p20, p21)); a2 += f.x + f.y;
        }

        int buf = (s & 1) * 384;
        if (!own) {
            uint32_t pa = (s & 1) ? pa1 : pa0;
            asm volatile("st.shared::cluster.f32 [%0], %1;" :: "r"(pa),         "f"(a0) : "memory");
            asm volatile("st.shared::cluster.f32 [%0], %1;" :: "r"(pa + 512u),  "f"(a1) : "memory");
            asm volatile("st.shared::cluster.f32 [%0], %1;" :: "r"(pa + 1024u), "f"(a2) : "memory");
        }
        asm volatile("barrier.cluster.arrive.aligned;" ::: "memory");
        asm volatile("barrier.cluster.wait.aligned;"   ::: "memory");
        if (own) {
            float ghr = a0 + recv[buf + jloc];
            float ghz = a1 + recv[buf + 128 + jloc];
            float ghn = a2 + recv[buf + 256 + jloc];
            float r = 1.f/(1.f + __expf(-(gir + ghr)));
            float z = 1.f/(1.f + __expf(-(giz + ghz)));
            float nn2 = tanhf(gin + r*(ghn + bn));
            h_reg = (1.f - z)*nn2 + z*h_reg;
            gout[((size_t)(n*LSEQ + tpos))*HDIM + jj] = h_reg;
            hh_s[jloc] = __float2half_rn(h_reg);
        }
        __syncthreads();
    }
}

// ---------------- combine + hidden_last (float4 vectorized) ----------------
__global__ void __launch_bounds__(256) combine_kernel(float* __restrict__ out) {
    const int comb4 = (LSEQ*NB*HDIM) >> 2;     // float4 count
    int idx4 = blockIdx.x*256 + threadIdx.x;
    if (idx4 < comb4) {
        int c0 = (idx4 & 63) * 4;
        int rem = idx4 >> 6;                   // l*32 + n
        int nn = rem & 31;
        int l = rem >> 5;
        size_t base = ((size_t)(nn*LSEQ + l)) << 8;
        float4 f = *(const float4*)&g_outf[base + c0];
        float4 br = *(const float4*)&g_outb[base + (252 - c0)];
        float4 v;
        v.x = 0.5f*(f.x + br.w);
        v.y = 0.5f*(f.y + br.z);
        v.z = 0.5f*(f.z + br.y);
        v.w = 0.5f*(f.w + br.x);
        v.x = v.x > 0.f ? v.x : 0.f;
        v.y = v.y > 0.f ? v.y : 0.f;
        v.z = v.z > 0.f ? v.z : 0.f;
        v.w = v.w > 0.f ? v.w : 0.f;
        *(float4*)&out[(size_t)idx4*4] = v;
    } else if (idx4 < comb4 + NB*HDIM) {
        int i2 = idx4 - comb4;
        int nn = i2 >> 8, c = i2 & 255;
        out[(size_t)LSEQ*NB*HDIM + i2] = g_outb[((size_t)(nn*LSEQ)) * HDIM + c];   // hT_b = out_b at t=0
    }
}

// ---------------- launch ----------------
extern "C" void kernel_launch(void* const* d_in, const int* in_sizes, int n_in,
                              void* d_out, int out_size) {
    const float* X     = (const float*)d_in[0];
    const float* W1    = (const float*)d_in[1];
    const float* b1    = (const float*)d_in[2];
    const float* W2    = (const float*)d_in[3];
    const float* b2    = (const float*)d_in[4];
    const float* Wih_f = (const float*)d_in[5];
    const float* Whh_f = (const float*)d_in[6];
    const float* bih_f = (const float*)d_in[7];
    const float* bhh_f = (const float*)d_in[8];
    const float* Wih_b = (const float*)d_in[9];
    const float* Whh_b = (const float*)d_in[10];
    const float* bih_b = (const float*)d_in[11];
    const float* bhh_b = (const float*)d_in[12];
    float* out = (float*)d_out;

    cudaFuncSetAttribute(tc_gemm_kernel, cudaFuncAttributeMaxDynamicSharedMemorySize, GEMM_SMEM);

    prep_kernel<<<1536, 256>>>(Whh_f, Whh_b, Wih_f, Wih_b, bih_f, bih_b, bhh_f, bhh_b, W2);
    conv1_kernel<<<dim3(NB, 8), 256>>>(X, W1, b1);
    cmat_kernel<<<dim3(12, 3), 256>>>();
    cconv_kernel<<<(NCOL*K2 + 255)/256, 256>>>();
    beta2_kernel<<<96, 256>>>(b2);
    amat_kernel<<<12288, 256>>>();
    tc_gemm_kernel<<<dim3(12, 512), 256, GEMM_SMEM>>>();
    gru_kernel<<<128, 256>>>();
    int total4 = ((LSEQ*NB*HDIM) >> 2) + NB*HDIM;
    combine_kernel<<<(total4 + 255)/256, 256>>>(out);
}